// round 1
// baseline (speedup 1.0000x reference)
#include <cuda_runtime.h>
#include <cstdint>

#define DDIM   64
#define BM     128
#define BN     128
#define EPITCH 132
#define TPB    256

__device__ float g_partial[1024];
__device__ float g_ce[8192];

static __device__ __forceinline__ unsigned long long pack2(float lo, float hi) {
    unsigned long long r;
    asm("mov.b64 %0, {%1, %2};" : "=l"(r) : "f"(lo), "f"(hi));
    return r;
}
static __device__ __forceinline__ void fma2(unsigned long long& d, unsigned long long a,
                                            unsigned long long b) {
    asm("fma.rn.f32x2 %0, %1, %2, %0;" : "+l"(d) : "l"(a), "l"(b));
}
static __device__ __forceinline__ float2 unpack2(unsigned long long v) {
    float lo, hi;
    asm("mov.b64 {%0, %1}, %2;" : "=f"(lo), "=f"(hi) : "l"(v));
    return make_float2(lo, hi);
}

// ||e_k||^2 for each code row
__global__ void ce_kernel(const float* __restrict__ cb, int K) {
    int k = blockIdx.x * blockDim.x + threadIdx.x;
    if (k >= K) return;
    const float4* p = reinterpret_cast<const float4*>(cb + (size_t)k * DDIM);
    float s = 0.f;
#pragma unroll
    for (int j = 0; j < 16; j++) {
        float4 v = p[j];
        s += v.x * v.x + v.y * v.y + v.z * v.z + v.w * v.w;
    }
    g_ce[k] = s;
}

// Fused distance GEMM + per-row argmin. Tile: 128 rows x 128 codes, D=64 resident.
// Accumulation in packed fp32 pairs (fma.rn.f32x2), pairing adjacent rows.
__global__ void __launch_bounds__(TPB, 2)
argmin_kernel(const float* __restrict__ x, const float* __restrict__ cb,
              float* __restrict__ out_idx, int K) {
    extern __shared__ float sm[];
    float* xs = sm;               // [DDIM][BM]     d-major, pitch 128
    float* es = sm + DDIM * BM;   // [DDIM][EPITCH] d-major, pitch 132

    const int t  = threadIdx.x;
    const int tx = t & 15;        // code-tile dimension
    const int ty = t >> 4;        // row-tile dimension
    const long rowblk = (long)blockIdx.x * BM;

    // Load + transpose the x tile (once per block). Each thread: 128B contiguous gmem.
    {
        int r = t >> 1, h = t & 1;
        const float4* src =
            reinterpret_cast<const float4*>(x + (size_t)(rowblk + r) * DDIM + h * 32);
#pragma unroll
        for (int j = 0; j < 8; j++) {
            float4 v = src[j];
            int d = h * 32 + 4 * j;
            xs[(d + 0) * BM + r] = v.x;
            xs[(d + 1) * BM + r] = v.y;
            xs[(d + 2) * BM + r] = v.z;
            xs[(d + 3) * BM + r] = v.w;
        }
    }

    float minv[8];
    int   mini[8];
#pragma unroll
    for (int i = 0; i < 8; i++) { minv[i] = 3.4e38f; mini[i] = 0; }

    for (int kc = 0; kc < K; kc += BN) {
        __syncthreads();
        // Load + transpose e tile for this chunk
        {
            int c = t >> 1, h = t & 1;
            const float4* src =
                reinterpret_cast<const float4*>(cb + (size_t)(kc + c) * DDIM + h * 32);
#pragma unroll
            for (int j = 0; j < 8; j++) {
                float4 v = src[j];
                int d = h * 32 + 4 * j;
                es[(d + 0) * EPITCH + c] = v.x;
                es[(d + 1) * EPITCH + c] = v.y;
                es[(d + 2) * EPITCH + c] = v.z;
                es[(d + 3) * EPITCH + c] = v.w;
            }
        }
        __syncthreads();

        unsigned long long acc[32];   // 4 row-pairs x 8 codes
#pragma unroll
        for (int i = 0; i < 32; i++) acc[i] = 0ull;

        const float* xbase = xs + ty * 8;
        const float* ebase = es + 4 * tx;

#pragma unroll 4
        for (int d = 0; d < DDIM; d++) {
            const float* xrow = xbase + d * BM;
            unsigned long long xr[4];
            {
                ulonglong2 a = *reinterpret_cast<const ulonglong2*>(xrow);
                ulonglong2 b = *reinterpret_cast<const ulonglong2*>(xrow + 4);
                xr[0] = a.x; xr[1] = a.y; xr[2] = b.x; xr[3] = b.y;
            }
            const float* erow = ebase + d * EPITCH;
            float4 e0 = *reinterpret_cast<const float4*>(erow);
            float4 e1 = *reinterpret_cast<const float4*>(erow + 64);
            unsigned long long ep[8];
            ep[0] = pack2(e0.x, e0.x); ep[1] = pack2(e0.y, e0.y);
            ep[2] = pack2(e0.z, e0.z); ep[3] = pack2(e0.w, e0.w);
            ep[4] = pack2(e1.x, e1.x); ep[5] = pack2(e1.y, e1.y);
            ep[6] = pack2(e1.z, e1.z); ep[7] = pack2(e1.w, e1.w);
#pragma unroll
            for (int i = 0; i < 4; i++)
#pragma unroll
                for (int j = 0; j < 8; j++)
                    fma2(acc[i * 8 + j], xr[i], ep[j]);
        }

        // Scores + running min. Codes per thread increase with j -> tie keeps lowest idx.
#pragma unroll
        for (int j = 0; j < 8; j++) {
            int cl = (j < 4) ? (4 * tx + j) : (64 + 4 * tx + (j - 4));
            int cg = kc + cl;
            float ce = __ldg(&g_ce[cg]);
#pragma unroll
            for (int i = 0; i < 4; i++) {
                float2 dd = unpack2(acc[i * 8 + j]);
                float s0 = fmaf(-2.f, dd.x, ce);
                float s1 = fmaf(-2.f, dd.y, ce);
                if (s0 < minv[2 * i])     { minv[2 * i] = s0;     mini[2 * i] = cg; }
                if (s1 < minv[2 * i + 1]) { minv[2 * i + 1] = s1; mini[2 * i + 1] = cg; }
            }
        }
    }

    // Cross-thread (tx) reduction per row, first-index tie-break.
    __syncthreads();
    float* rv = sm;                                  // BM*16 floats
    int*   ri = reinterpret_cast<int*>(sm + BM * 16);
#pragma unroll
    for (int i = 0; i < 8; i++) {
        int row = ty * 8 + i;
        rv[row * 16 + tx] = minv[i];
        ri[row * 16 + tx] = mini[i];
    }
    __syncthreads();
    if (t < BM) {
        float bv = rv[t * 16];
        int   bi = ri[t * 16];
#pragma unroll
        for (int j = 1; j < 16; j++) {
            float v  = rv[t * 16 + j];
            int   ii = ri[t * 16 + j];
            if (v < bv || (v == bv && ii < bi)) { bv = v; bi = ii; }
        }
        out_idx[rowblk + t] = (float)bi;
    }
}

// Gather quantized rows (== quantized_st forward value) + per-block partial of sum((x-q)^2)
__global__ void gather_loss_kernel(const float* __restrict__ x, const float* __restrict__ cb,
                                   const float* __restrict__ idxf, float* __restrict__ outq) {
    __shared__ float rs[256];
    int t = threadIdx.x;
    int rl = t >> 2, seg = t & 3;
    long row = (long)blockIdx.x * 64 + rl;
    int k = (int)idxf[row];
    const float4* q  = reinterpret_cast<const float4*>(cb + (size_t)k * DDIM + seg * 16);
    const float4* xi = reinterpret_cast<const float4*>(x + (size_t)row * DDIM + seg * 16);
    float4* o = reinterpret_cast<float4*>(outq + (size_t)row * DDIM + seg * 16);
    float s = 0.f;
#pragma unroll
    for (int j = 0; j < 4; j++) {
        float4 qv = q[j], xv = xi[j];
        o[j] = qv;
        float dx = xv.x - qv.x, dy = xv.y - qv.y, dz = xv.z - qv.z, dw = xv.w - qv.w;
        s += dx * dx + dy * dy + dz * dz + dw * dw;
    }
    rs[t] = s;
    __syncthreads();
    for (int off = 128; off > 0; off >>= 1) {
        if (t < off) rs[t] += rs[t + off];
        __syncthreads();
    }
    if (t == 0) g_partial[blockIdx.x] = rs[0];
}

__global__ void loss_finalize_kernel(float* __restrict__ out_loss, int nparts, float scale) {
    __shared__ float rs[256];
    int t = threadIdx.x;
    float s = 0.f;
    for (int i = t; i < nparts; i += 256) s += g_partial[i];
    rs[t] = s;
    __syncthreads();
    for (int off = 128; off > 0; off >>= 1) {
        if (t < off) rs[t] += rs[t + off];
        __syncthreads();
    }
    if (t == 0) out_loss[0] = rs[0] * scale;
}

extern "C" void kernel_launch(void* const* d_in, const int* in_sizes, int n_in,
                              void* d_out, int out_size) {
    const float* x  = (const float*)d_in[0];
    const float* cb = (const float*)d_in[1];
    const int B = in_sizes[0] / DDIM;   // 65536
    const int K = in_sizes[1] / DDIM;   // 8192

    float* out      = (float*)d_out;
    float* out_q    = out;                      // [B*D] quantized_st (== codebook gather)
    float* out_loss = out + (size_t)B * DDIM;   // [1]   vq_loss
    float* out_idx  = out_loss + 1;             // [B]   encoding indices (as float)

    ce_kernel<<<(K + 255) / 256, 256>>>(cb, K);

    const int smem_bytes = (DDIM * BM + DDIM * EPITCH) * (int)sizeof(float);  // 66560
    cudaFuncSetAttribute(argmin_kernel, cudaFuncAttributeMaxDynamicSharedMemorySize, smem_bytes);
    argmin_kernel<<<B / BM, TPB, smem_bytes>>>(x, cb, out_idx, K);

    gather_loss_kernel<<<B / 64, 256>>>(x, cb, out_idx, out_q);
    loss_finalize_kernel<<<1, 256>>>(out_loss, B / 64, 1.25f / ((float)B * DDIM));
}

// round 3
// speedup vs baseline: 1.8328x; 1.8328x over previous
#include <cuda_runtime.h>
#include <cuda_bf16.h>
#include <cstdint>

#define DB    64
#define NB    65536
#define NK    8192
#define BM    128
#define NCH   64            // K chunks of 128 codes
#define TPB   256

// smem layout (bytes): ce[8192]f32 @0 (32KB) | A 128x256B @32768 | B 2x32KB @65536
#define SM_A   32768
#define SM_B   65536
#define SM_TOT 131072

// ---- device globals ----
__device__ __nv_bfloat16 g_e[(size_t)NK * 128];   // [code][hi 64 | lo 64]
__device__ float g_ce[NK];
__device__ int   g_c1[NB];
__device__ int   g_c2[NB];
__device__ float g_partial[1024];

static __device__ __forceinline__ uint32_t smem_u32(const void* p) {
    uint32_t a;
    asm("{ .reg .u64 t; cvta.to.shared.u64 t, %1; cvt.u32.u64 %0, t; }" : "=r"(a) : "l"(p));
    return a;
}

#define CP_ASYNC16(dst, src) asm volatile("cp.async.cg.shared.global [%0], [%1], 16;" :: "r"(dst), "l"(src))
#define CP_COMMIT()          asm volatile("cp.async.commit_group;" ::: "memory")
#define CP_WAITG(n)          asm volatile("cp.async.wait_group %0;" :: "n"(n) : "memory")

#define LDSM_X4(r0, r1, r2, r3, a) \
    asm volatile("ldmatrix.sync.aligned.m8n8.x4.shared.b16 {%0,%1,%2,%3}, [%4];" \
                 : "=r"(r0), "=r"(r1), "=r"(r2), "=r"(r3) : "r"(a))

#define MMA16816(d, a0, a1, a2, a3, b0, b1) \
    asm volatile("mma.sync.aligned.m16n8k16.row.col.f32.bf16.bf16.f32 " \
                 "{%0,%1,%2,%3}, {%4,%5,%6,%7}, {%8,%9}, {%0,%1,%2,%3};" \
                 : "+f"((d)[0]), "+f"((d)[1]), "+f"((d)[2]), "+f"((d)[3]) \
                 : "r"(a0), "r"(a1), "r"(a2), "r"(a3), "r"(b0), "r"(b1))

#define INS(sv, si, V1, I1, V2, I2) do {                                   \
    if ((sv) < (V1) || ((sv) == (V1) && (si) < (I1))) {                    \
        V2 = V1; I2 = I1; V1 = (sv); I1 = (si);                            \
    } else if ((sv) < (V2) || ((sv) == (V2) && (si) < (I2))) {             \
        V2 = (sv); I2 = (si);                                              \
    } } while (0)

static __device__ __forceinline__ void split_bf16(float f, unsigned short& hb, unsigned short& lb) {
    __nv_bfloat16 h = __float2bfloat16_rn(f);
    __nv_bfloat16 l = __float2bfloat16_rn(f - __bfloat162float(h));
    hb = __bfloat16_as_ushort(h);
    lb = __bfloat16_as_ushort(l);
}

// ============ codebook pack: bf16 hi|lo per code row ============
__global__ void conv_cb_kernel(const float* __restrict__ cb) {
    size_t i = (size_t)blockIdx.x * blockDim.x + threadIdx.x;  // float4 id, 131072 total
    float4 v = reinterpret_cast<const float4*>(cb)[i];
    int code = (int)(i >> 4), fc = (int)(i & 15);
    float f[4] = {v.x, v.y, v.z, v.w};
    unsigned short hb[4], lb[4];
#pragma unroll
    for (int j = 0; j < 4; j++) split_bf16(f[j], hb[j], lb[j]);
    uint2 H, L;
    H.x = (uint32_t)hb[0] | ((uint32_t)hb[1] << 16);
    H.y = (uint32_t)hb[2] | ((uint32_t)hb[3] << 16);
    L.x = (uint32_t)lb[0] | ((uint32_t)lb[1] << 16);
    L.y = (uint32_t)lb[2] | ((uint32_t)lb[3] << 16);
    *reinterpret_cast<uint2*>(g_e + (size_t)code * 128 + fc * 4)      = H;
    *reinterpret_cast<uint2*>(g_e + (size_t)code * 128 + 64 + fc * 4) = L;
}

__global__ void ce_kernel(const float* __restrict__ cb) {
    int k = blockIdx.x * blockDim.x + threadIdx.x;
    const float4* p = reinterpret_cast<const float4*>(cb + (size_t)k * DB);
    float s = 0.f;
#pragma unroll
    for (int j = 0; j < 16; j++) {
        float4 v = p[j];
        s += v.x * v.x + v.y * v.y + v.z * v.z + v.w * v.w;
    }
    g_ce[k] = s;
}

// ============ fused HMMA distance + per-row top-2 ============
__global__ void __launch_bounds__(TPB, 1)
argmin_mma_kernel(const float* __restrict__ x) {
    extern __shared__ char smem[];
    const uint32_t sb = smem_u32(smem);
    const int t = threadIdx.x;
    const int wid = t >> 5, lane = t & 31;

    // ce table -> smem
    {
        float4* d = reinterpret_cast<float4*>(smem);
        const float4* s = reinterpret_cast<const float4*>(g_ce);
        for (int i = t; i < 2048; i += TPB) d[i] = s[i];
    }
    // A tile: load x fp32, split to -2x hi/lo bf16, swizzled store
    {
        const float4* xs = reinterpret_cast<const float4*>(x + (size_t)blockIdx.x * BM * DB);
#pragma unroll
        for (int i = 0; i < 8; i++) {
            int id = t + i * TPB;
            int r = id >> 4, fc = id & 15;
            float4 v = xs[id];
            float f[4] = {-2.f * v.x, -2.f * v.y, -2.f * v.z, -2.f * v.w};
            unsigned short hb[4], lb[4];
#pragma unroll
            for (int j = 0; j < 4; j++) split_bf16(f[j], hb[j], lb[j]);
            uint2 H, L;
            H.x = (uint32_t)hb[0] | ((uint32_t)hb[1] << 16);
            H.y = (uint32_t)hb[2] | ((uint32_t)hb[3] << 16);
            L.x = (uint32_t)lb[0] | ((uint32_t)lb[1] << 16);
            L.y = (uint32_t)lb[2] | ((uint32_t)lb[3] << 16);
            char* base = smem + SM_A + r * 256 + (fc & 1) * 8;
            *reinterpret_cast<uint2*>(base + (((fc >> 1) ^ (r & 7)) << 4))       = H;
            *reinterpret_cast<uint2*>(base + (((8 + (fc >> 1)) ^ (r & 7)) << 4)) = L;
        }
    }
    __syncthreads();

    // lane-invariant addressing
    const int RW = wid * 16;                                  // warp row base
    const int rA = RW + ((lane >> 3) & 1) * 8 + (lane & 7);   // ldmatrix A row
    const uint32_t aRowBase = sb + SM_A + rA * 256;
    const int aXor = rA & 7;
    const int akHalf = lane >> 4;                             // +1 chunk for lanes 16-31
    const int nb_off = ((lane >> 4) & 1) * 8 + (lane & 7);    // ldmatrix B n within 16-grp
    const int kb = (lane >> 3) & 1;                           // +1 k-chunk for lanes 8-15,24-31
    const int nX = nb_off & 7;
    const uint32_t bRow = nb_off * 256;

    float v1a = 3.4e38f, v2a = 3.4e38f, v1b = 3.4e38f, v2b = 3.4e38f;
    int i1a = 0, i2a = 0, i1b = 0, i2b = 0;

    // B chunk loader (cp.async, 32KB per chunk)
    auto load_B = [&](int kc, int buf) {
        const char* gsrc = reinterpret_cast<const char*>(g_e) + (size_t)kc * 128 * 256;
        uint32_t dbase = sb + SM_B + buf * 32768;
#pragma unroll
        for (int i = 0; i < 8; i++) {
            int id = t + i * TPB;
            int r = id >> 4, c = id & 15;
            uint32_t dst = dbase + r * 256 + ((c ^ (r & 7)) << 4);
            CP_ASYNC16(dst, gsrc + r * 256 + c * 16);
        }
    };

    load_B(0, 0);
    CP_COMMIT();

    for (int kc = 0; kc < NCH; kc++) {
        const int buf = kc & 1;
        if (kc < NCH - 1) {
            load_B(kc + 1, buf ^ 1);
            CP_COMMIT();
            CP_WAITG(1);
        } else {
            CP_WAITG(0);
        }
        __syncthreads();

        float acc[64];
#pragma unroll
        for (int i = 0; i < 64; i++) acc[i] = 0.f;
        const uint32_t bBuf = sb + SM_B + buf * 32768;

#pragma unroll
        for (int ks = 0; ks < 12; ks++) {
            const int term = ks >> 2, kk = ks & 3;
            const int ac = (term == 2 ? 8 : 0) + kk * 2;   // A: hi,hi,lo
            const int bc = (term == 1 ? 8 : 0) + kk * 2;   // B: hi,lo,hi
            uint32_t a0, a1, a2, a3;
            LDSM_X4(a0, a1, a2, a3, aRowBase + (((ac + akHalf) ^ aXor) << 4));
            uint32_t br[8][4];
#pragma unroll
            for (int g = 0; g < 8; g++) {
                LDSM_X4(br[g][0], br[g][1], br[g][2], br[g][3],
                        bBuf + g * 4096 + bRow + (((bc + kb) ^ nX) << 4));
            }
#pragma unroll
            for (int nf = 0; nf < 16; nf++) {
                const int g = nf >> 1, s = (nf & 1) * 2;
                MMA16816(&acc[nf * 4], a0, a1, a2, a3, br[g][s], br[g][s + 1]);
            }
        }

        // epilogue: add ce, track top-2 per row slot
        const float2* cef = reinterpret_cast<const float2*>(smem);
        const int colq = kc * 128 + 2 * (lane & 3);
#pragma unroll
        for (int nf = 0; nf < 16; nf++) {
            float2 ce2 = cef[(kc * 128 + nf * 8 + 2 * (lane & 3)) >> 1];
            const int c0 = colq + nf * 8;
            float s;
            s = acc[nf * 4 + 0] + ce2.x;
            if (s < v2a) { if (s < v1a) { v2a = v1a; i2a = i1a; v1a = s; i1a = c0; } else { v2a = s; i2a = c0; } }
            s = acc[nf * 4 + 1] + ce2.y;
            if (s < v2a) { if (s < v1a) { v2a = v1a; i2a = i1a; v1a = s; i1a = c0 + 1; } else { v2a = s; i2a = c0 + 1; } }
            s = acc[nf * 4 + 2] + ce2.x;
            if (s < v2b) { if (s < v1b) { v2b = v1b; i2b = i1b; v1b = s; i1b = c0; } else { v2b = s; i2b = c0; } }
            s = acc[nf * 4 + 3] + ce2.y;
            if (s < v2b) { if (s < v1b) { v2b = v1b; i2b = i1b; v1b = s; i1b = c0 + 1; } else { v2b = s; i2b = c0 + 1; } }
        }
        __syncthreads();
    }

    // merge top-2 across the 4 lanes of each quad (same rows)
#pragma unroll
    for (int off = 1; off <= 2; off <<= 1) {
        float ov1 = __shfl_xor_sync(0xffffffffu, v1a, off);
        int   oi1 = __shfl_xor_sync(0xffffffffu, i1a, off);
        float ov2 = __shfl_xor_sync(0xffffffffu, v2a, off);
        int   oi2 = __shfl_xor_sync(0xffffffffu, i2a, off);
        INS(ov1, oi1, v1a, i1a, v2a, i2a);
        INS(ov2, oi2, v1a, i1a, v2a, i2a);
        ov1 = __shfl_xor_sync(0xffffffffu, v1b, off);
        oi1 = __shfl_xor_sync(0xffffffffu, i1b, off);
        ov2 = __shfl_xor_sync(0xffffffffu, v2b, off);
        oi2 = __shfl_xor_sync(0xffffffffu, i2b, off);
        INS(ov1, oi1, v1b, i1b, v2b, i2b);
        INS(ov2, oi2, v1b, i1b, v2b, i2b);
    }
    if ((lane & 3) == 0) {
        const int row = blockIdx.x * BM + RW + (lane >> 2);
        g_c1[row] = i1a; g_c2[row] = i2a;
        g_c1[row + 8] = i1b; g_c2[row + 8] = i2b;
    }
}

// ============ exact rescore + gather + loss ============
__global__ void rescore_gather_loss(const float* __restrict__ x, const float* __restrict__ cb,
                                    float* __restrict__ outq, float* __restrict__ out_idx) {
    __shared__ float rs[256];
    const int t = threadIdx.x;
    const int rl = t >> 2, seg = t & 3;
    const size_t row = (size_t)blockIdx.x * 64 + rl;
    const int c1 = g_c1[row], c2 = g_c2[row];

    const float4* xp = reinterpret_cast<const float4*>(x + row * DB + seg * 16);
    const float4* p1 = reinterpret_cast<const float4*>(cb + (size_t)c1 * DB + seg * 16);
    const float4* p2 = reinterpret_cast<const float4*>(cb + (size_t)c2 * DB + seg * 16);
    float d1 = 0.f, d2 = 0.f;
    float4 xv[4];
#pragma unroll
    for (int j = 0; j < 4; j++) {
        xv[j] = xp[j];
        float4 a = p1[j], b = p2[j];
        d1 += xv[j].x * a.x + xv[j].y * a.y + xv[j].z * a.z + xv[j].w * a.w;
        d2 += xv[j].x * b.x + xv[j].y * b.y + xv[j].z * b.z + xv[j].w * b.w;
    }
    d1 += __shfl_xor_sync(0xffffffffu, d1, 1); d1 += __shfl_xor_sync(0xffffffffu, d1, 2);
    d2 += __shfl_xor_sync(0xffffffffu, d2, 1); d2 += __shfl_xor_sync(0xffffffffu, d2, 2);
    const float s1 = fmaf(-2.f, d1, g_ce[c1]);
    const float s2 = fmaf(-2.f, d2, g_ce[c2]);
    const int k = (s2 < s1 || (s2 == s1 && c2 < c1)) ? c2 : c1;

    const float4* pk = reinterpret_cast<const float4*>(cb + (size_t)k * DB + seg * 16);
    float4* o = reinterpret_cast<float4*>(outq + row * DB + seg * 16);
    float loss = 0.f;
#pragma unroll
    for (int j = 0; j < 4; j++) {
        float4 q = pk[j];
        o[j] = q;
        float dx = xv[j].x - q.x, dy = xv[j].y - q.y, dz = xv[j].z - q.z, dw = xv[j].w - q.w;
        loss += dx * dx + dy * dy + dz * dz + dw * dw;
    }
    if (seg == 0) out_idx[row] = (float)k;

    rs[t] = loss;
    __syncthreads();
    for (int off = 128; off > 0; off >>= 1) {
        if (t < off) rs[t] += rs[t + off];
        __syncthreads();
    }
    if (t == 0) g_partial[blockIdx.x] = rs[0];
}

__global__ void loss_finalize_kernel(float* __restrict__ out_loss, int nparts, float scale) {
    __shared__ float rs[256];
    int t = threadIdx.x;
    float s = 0.f;
    for (int i = t; i < nparts; i += 256) s += g_partial[i];
    rs[t] = s;
    __syncthreads();
    for (int off = 128; off > 0; off >>= 1) {
        if (t < off) rs[t] += rs[t + off];
        __syncthreads();
    }
    if (t == 0) out_loss[0] = rs[0] * scale;
}

extern "C" void kernel_launch(void* const* d_in, const int* in_sizes, int n_in,
                              void* d_out, int out_size) {
    const float* x  = (const float*)d_in[0];
    const float* cb = (const float*)d_in[1];
    const int B = in_sizes[0] / DB;   // 65536
    (void)n_in; (void)out_size;

    float* out      = (float*)d_out;
    float* out_q    = out;
    float* out_loss = out + (size_t)B * DB;
    float* out_idx  = out_loss + 1;

    conv_cb_kernel<<<(NK * 16) / 256, 256>>>(cb);
    ce_kernel<<<NK / 256, 256>>>(cb);

    cudaFuncSetAttribute(argmin_mma_kernel, cudaFuncAttributeMaxDynamicSharedMemorySize, SM_TOT);
    argmin_mma_kernel<<<B / BM, TPB, SM_TOT>>>(x);

    rescore_gather_loss<<<B / 64, 256>>>(x, cb, out_q, out_idx);
    loss_finalize_kernel<<<1, 256>>>(out_loss, B / 64, 1.25f / ((float)B * DB));
}

// round 5
// speedup vs baseline: 1.9844x; 1.0827x over previous
#include <cuda_runtime.h>
#include <cuda_fp16.h>
#include <cstdint>

#define DB    64
#define NB    65536
#define NK    8192
#define BM    128
#define NCH   64            // K chunks of 128 codes
#define TPB   256

// smem (bytes): ce 32KB @0 | A 16KB @32768 | B 4x16KB @49152 | cand 6KB @114688
#define SM_A    32768
#define SM_B    49152
#define SM_CAND 114688
#define SM_TOT  120832

__device__ __half g_e[(size_t)NK * DB];    // codebook fp16, row-contiguous 128B
__device__ float g_ce[NK];
__device__ float g_partial[1024];

static __device__ __forceinline__ uint32_t smem_u32(const void* p) {
    uint32_t a;
    asm("{ .reg .u64 t; cvta.to.shared.u64 t, %1; cvt.u32.u64 %0, t; }" : "=r"(a) : "l"(p));
    return a;
}

#define CP_ASYNC16(dst, src) asm volatile("cp.async.cg.shared.global [%0], [%1], 16;" :: "r"(dst), "l"(src))
#define CP_COMMIT()          asm volatile("cp.async.commit_group;" ::: "memory")
#define CP_WAITG(n)          asm volatile("cp.async.wait_group %0;" :: "n"(n) : "memory")

#define LDSM_X4(r0, r1, r2, r3, a) \
    asm volatile("ldmatrix.sync.aligned.m8n8.x4.shared.b16 {%0,%1,%2,%3}, [%4];" \
                 : "=r"(r0), "=r"(r1), "=r"(r2), "=r"(r3) : "r"(a))

#define MMA16816(d, a0, a1, a2, a3, b0, b1) \
    asm volatile("mma.sync.aligned.m16n8k16.row.col.f32.f16.f16.f32 " \
                 "{%0,%1,%2,%3}, {%4,%5,%6,%7}, {%8,%9}, {%0,%1,%2,%3};" \
                 : "+f"((d)[0]), "+f"((d)[1]), "+f"((d)[2]), "+f"((d)[3]) \
                 : "r"(a0), "r"(a1), "r"(a2), "r"(a3), "r"(b0), "r"(b1))

// top-3 insert (value, index) with lowest-index tie keep
#define TOP3(s, c, V1, I1, V2, I2, V3, I3) do {                    \
    if ((s) < (V3)) {                                              \
        if ((s) < (V1))      { V3=V2; I3=I2; V2=V1; I2=I1; V1=(s); I1=(c); } \
        else if ((s) < (V2)) { V3=V2; I3=I2; V2=(s); I2=(c); }     \
        else                 { V3=(s); I3=(c); }                   \
    } } while (0)

// ============ codebook -> fp16 pack ============
__global__ void conv_cb_kernel(const float* __restrict__ cb) {
    size_t i = (size_t)blockIdx.x * blockDim.x + threadIdx.x;  // float4 id (131072)
    float4 v = reinterpret_cast<const float4*>(cb)[i];
    __half2 h0 = __floats2half2_rn(v.x, v.y);
    __half2 h1 = __floats2half2_rn(v.z, v.w);
    uint2 H;
    H.x = *reinterpret_cast<uint32_t*>(&h0);
    H.y = *reinterpret_cast<uint32_t*>(&h1);
    *reinterpret_cast<uint2*>(g_e + i * 4) = H;
}

__global__ void ce_kernel(const float* __restrict__ cb) {
    int k = blockIdx.x * blockDim.x + threadIdx.x;
    const float4* p = reinterpret_cast<const float4*>(cb + (size_t)k * DB);
    float s = 0.f;
#pragma unroll
    for (int j = 0; j < 16; j++) {
        float4 v = p[j];
        s += v.x * v.x + v.y * v.y + v.z * v.z + v.w * v.w;
    }
    g_ce[k] = s;
}

// ============ fused HMMA distance + top-3 + exact rescore ============
__global__ void __launch_bounds__(TPB, 1)
argmin_mma_kernel(const float* __restrict__ x, const float* __restrict__ cb,
                  float* __restrict__ out_idx) {
    extern __shared__ char smem[];
    const uint32_t sb = smem_u32(smem);
    const int t = threadIdx.x;
    const int wid = t >> 5, lane = t & 31;

    // B chunk loader: 16KB = 1024 x 16B, 4 per thread
    auto load_B = [&](int kc, int stage) {
        const char* gsrc = reinterpret_cast<const char*>(g_e) + (size_t)kc * 128 * 128;
        uint32_t dbase = sb + SM_B + stage * 16384;
#pragma unroll
        for (int i = 0; i < 4; i++) {
            int id = t + i * TPB;
            int r = id >> 3, c = id & 7;
            CP_ASYNC16(dbase + r * 128 + ((c ^ (r & 7)) << 4), gsrc + r * 128 + c * 16);
        }
    };
    load_B(0, 0); CP_COMMIT();
    load_B(1, 1); CP_COMMIT();
    load_B(2, 2); CP_COMMIT();

    // ce -> smem
    {
        float4* d = reinterpret_cast<float4*>(smem);
        const float4* s = reinterpret_cast<const float4*>(g_ce);
        for (int i = t; i < 2048; i += TPB) d[i] = s[i];
    }
    // A tile: -2x fp16, swizzled 128B rows
    {
        const float4* xs = reinterpret_cast<const float4*>(x + (size_t)blockIdx.x * BM * DB);
#pragma unroll
        for (int i = 0; i < 8; i++) {
            int id = t + i * TPB;          // 2048 float4
            int r = id >> 4, fc = id & 15;
            float4 v = xs[id];
            __half2 h0 = __floats2half2_rn(-2.f * v.x, -2.f * v.y);
            __half2 h1 = __floats2half2_rn(-2.f * v.z, -2.f * v.w);
            uint2 H;
            H.x = *reinterpret_cast<uint32_t*>(&h0);
            H.y = *reinterpret_cast<uint32_t*>(&h1);
            int s = fc >> 1, hh = fc & 1;
            *reinterpret_cast<uint2*>(smem + SM_A + r * 128 + ((s ^ (r & 7)) << 4) + hh * 8) = H;
        }
    }

    // lane-invariant addressing (validated pattern from R3)
    const int RW = wid * 16;
    const int rA = RW + ((lane >> 3) & 1) * 8 + (lane & 7);
    const uint32_t aRowBase = sb + SM_A + rA * 128;
    const int aXor = rA & 7;
    const int akHalf = lane >> 4;
    const int nb_off = ((lane >> 4) & 1) * 8 + (lane & 7);
    const int kb = (lane >> 3) & 1;
    const int nX = nb_off & 7;
    const uint32_t bRow = nb_off * 128;

    float v1a = 3.4e38f, v2a = 3.4e38f, v3a = 3.4e38f;
    float v1b = 3.4e38f, v2b = 3.4e38f, v3b = 3.4e38f;
    int i1a = 0, i2a = 0, i3a = 0, i1b = 0, i2b = 0, i3b = 0;

    for (int kc = 0; kc < NCH; kc++) {
        const int stage = kc & 3;
        CP_WAITG(2);
        __syncthreads();

        float acc[64];
#pragma unroll
        for (int i = 0; i < 64; i++) acc[i] = 0.f;
        const uint32_t bBuf = sb + SM_B + stage * 16384;

#pragma unroll
        for (int kk = 0; kk < 4; kk++) {
            uint32_t a0, a1, a2, a3;
            LDSM_X4(a0, a1, a2, a3, aRowBase + (((2 * kk + akHalf) ^ aXor) << 4));
            uint32_t br[8][4];
#pragma unroll
            for (int g = 0; g < 8; g++) {
                LDSM_X4(br[g][0], br[g][1], br[g][2], br[g][3],
                        bBuf + g * 2048 + bRow + (((2 * kk + kb) ^ nX) << 4));
            }
#pragma unroll
            for (int nf = 0; nf < 16; nf++) {
                const int g = nf >> 1, s = (nf & 1) * 2;
                MMA16816(&acc[nf * 4], a0, a1, a2, a3, br[g][s], br[g][s + 1]);
            }
        }

        // epilogue: score = acc + ||e||^2, per-thread top-3 (two row slices)
        const float2* cef = reinterpret_cast<const float2*>(smem);
        const int colq = kc * 128 + 2 * (lane & 3);
#pragma unroll
        for (int nf = 0; nf < 16; nf++) {
            float2 ce2 = cef[(kc * 128 + nf * 8) / 2 + (lane & 3)];
            const int c0 = colq + nf * 8;
            float s;
            s = acc[nf * 4 + 0] + ce2.x; TOP3(s, c0,     v1a, i1a, v2a, i2a, v3a, i3a);
            s = acc[nf * 4 + 1] + ce2.y; TOP3(s, c0 + 1, v1a, i1a, v2a, i2a, v3a, i3a);
            s = acc[nf * 4 + 2] + ce2.x; TOP3(s, c0,     v1b, i1b, v2b, i2b, v3b, i3b);
            s = acc[nf * 4 + 3] + ce2.y; TOP3(s, c0 + 1, v1b, i1b, v2b, i2b, v3b, i3b);
        }

        if (kc + 3 < NCH) load_B(kc + 3, (kc + 3) & 3);
        CP_COMMIT();   // unconditional: keeps group count uniform
    }

    // dump 12 candidates/row (3 per quad lane)
    {
        int* cand = reinterpret_cast<int*>(smem + SM_CAND);
        const int q = lane & 3;
        const int ra = RW + (lane >> 2), rb = ra + 8;
        cand[ra * 12 + q * 3 + 0] = i1a;
        cand[ra * 12 + q * 3 + 1] = i2a;
        cand[ra * 12 + q * 3 + 2] = i3a;
        cand[rb * 12 + q * 3 + 0] = i1b;
        cand[rb * 12 + q * 3 + 1] = i2b;
        cand[rb * 12 + q * 3 + 2] = i3b;
    }
    __syncthreads();

    // exact fp32 rescore: 2 threads/row, 32 dims each, 12 candidates
    {
        const int r = t >> 1, half = t & 1;
        const int* cand = reinterpret_cast<const int*>(smem + SM_CAND);
        const float* ce = reinterpret_cast<const float*>(smem);
        float xr[32];
        const float4* xp = reinterpret_cast<const float4*>(
            x + ((size_t)blockIdx.x * BM + r) * DB + half * 32);
#pragma unroll
        for (int j = 0; j < 8; j++) {
            float4 v = xp[j];
            xr[j * 4] = v.x; xr[j * 4 + 1] = v.y; xr[j * 4 + 2] = v.z; xr[j * 4 + 3] = v.w;
        }
        float best = 3.4e38f;
        int bi = NK;
#pragma unroll 1
        for (int j = 0; j < 12; j++) {
            const int c = cand[r * 12 + j];
            const float4* ep = reinterpret_cast<const float4*>(cb + (size_t)c * DB + half * 32);
            float dot = 0.f;
#pragma unroll
            for (int u = 0; u < 8; u++) {
                float4 e = ep[u];
                dot += xr[u * 4] * e.x + xr[u * 4 + 1] * e.y + xr[u * 4 + 2] * e.z + xr[u * 4 + 3] * e.w;
            }
            dot += __shfl_xor_sync(0xffffffffu, dot, 1);
            const float score = fmaf(-2.f, dot, ce[c]);
            if (score < best || (score == best && c < bi)) { best = score; bi = c; }
        }
        if (half == 0) out_idx[(size_t)blockIdx.x * BM + r] = (float)bi;
    }
}

// ============ gather + loss ============
__global__ void gather_loss_kernel(const float* __restrict__ x, const float* __restrict__ cb,
                                   const float* __restrict__ idxf, float* __restrict__ outq) {
    __shared__ float rs[256];
    const int t = threadIdx.x;
    const int rl = t >> 2, seg = t & 3;
    const size_t row = (size_t)blockIdx.x * 64 + rl;
    const int k = (int)idxf[row];
    const float4* q  = reinterpret_cast<const float4*>(cb + (size_t)k * DB + seg * 16);
    const float4* xi = reinterpret_cast<const float4*>(x + row * DB + seg * 16);
    float4* o = reinterpret_cast<float4*>(outq + row * DB + seg * 16);
    float s = 0.f;
#pragma unroll
    for (int j = 0; j < 4; j++) {
        float4 qv = q[j], xv = xi[j];
        o[j] = qv;
        float dx = xv.x - qv.x, dy = xv.y - qv.y, dz = xv.z - qv.z, dw = xv.w - qv.w;
        s += dx * dx + dy * dy + dz * dz + dw * dw;
    }
    rs[t] = s;
    __syncthreads();
    for (int off = 128; off > 0; off >>= 1) {
        if (t < off) rs[t] += rs[t + off];
        __syncthreads();
    }
    if (t == 0) g_partial[blockIdx.x] = rs[0];
}

__global__ void loss_finalize_kernel(float* __restrict__ out_loss, int nparts, float scale) {
    __shared__ float rs[256];
    int t = threadIdx.x;
    float s = 0.f;
    for (int i = t; i < nparts; i += 256) s += g_partial[i];
    rs[t] = s;
    __syncthreads();
    for (int off = 128; off > 0; off >>= 1) {
        if (t < off) rs[t] += rs[t + off];
        __syncthreads();
    }
    if (t == 0) out_loss[0] = rs[0] * scale;
}

extern "C" void kernel_launch(void* const* d_in, const int* in_sizes, int n_in,
                              void* d_out, int out_size) {
    const float* x  = (const float*)d_in[0];
    const float* cb = (const float*)d_in[1];
    const int B = in_sizes[0] / DB;   // 65536
    (void)n_in; (void)out_size;

    float* out      = (float*)d_out;
    float* out_q    = out;
    float* out_loss = out + (size_t)B * DB;
    float* out_idx  = out_loss + 1;

    conv_cb_kernel<<<(NK * 16) / 256, 256>>>(cb);
    ce_kernel<<<NK / 256, 256>>>(cb);

    cudaFuncSetAttribute(argmin_mma_kernel, cudaFuncAttributeMaxDynamicSharedMemorySize, SM_TOT);
    argmin_mma_kernel<<<B / BM, TPB, SM_TOT>>>(x, cb, out_idx);

    gather_loss_kernel<<<B / 64, 256>>>(x, cb, out_idx, out_q);
    loss_finalize_kernel<<<1, 256>>>(out_loss, B / 64, 1.25f / ((float)B * DB));
}

// round 6
// speedup vs baseline: 3.6340x; 1.8313x over previous
#include <cuda_runtime.h>
#include <cuda_fp16.h>
#include <cstdint>

#define DB    64
#define NB    65536
#define NK    8192
#define BM    128
#define NCH   64            // K chunks of 128 codes
#define TPB   256

// smem (bytes): A 16KB @0 | cx 512B @16384 | B stages 4x16896 @16896 | cand 6KB @84480
#define SM_CX    16384
#define SM_BST   16896
#define STAGE_SZ 16896      // 16KB B + 512B ce
#define SM_CAND  84480
#define SM_TOT   90624

__device__ __half g_e[(size_t)NK * DB];    // codebook fp16, row-contiguous 128B
__device__ float g_ce[NK];
__device__ float g_partial[1024];

static __device__ __forceinline__ uint32_t smem_u32(const void* p) {
    uint32_t a;
    asm("{ .reg .u64 t; cvta.to.shared.u64 t, %1; cvt.u32.u64 %0, t; }" : "=r"(a) : "l"(p));
    return a;
}

#define CP_ASYNC16(dst, src) asm volatile("cp.async.cg.shared.global [%0], [%1], 16;" :: "r"(dst), "l"(src))
#define CP_COMMIT()          asm volatile("cp.async.commit_group;" ::: "memory")
#define CP_WAITG(n)          asm volatile("cp.async.wait_group %0;" :: "n"(n) : "memory")

#define LDSM_X4(r0, r1, r2, r3, a) \
    asm volatile("ldmatrix.sync.aligned.m8n8.x4.shared.b16 {%0,%1,%2,%3}, [%4];" \
                 : "=r"(r0), "=r"(r1), "=r"(r2), "=r"(r3) : "r"(a))

#define MMA16816(d, a0, a1, a2, a3, b0, b1) \
    asm volatile("mma.sync.aligned.m16n8k16.row.col.f32.f16.f16.f32 " \
                 "{%0,%1,%2,%3}, {%4,%5,%6,%7}, {%8,%9}, {%0,%1,%2,%3};" \
                 : "+f"((d)[0]), "+f"((d)[1]), "+f"((d)[2]), "+f"((d)[3]) \
                 : "r"(a0), "r"(a1), "r"(a2), "r"(a3), "r"(b0), "r"(b1))

// branchless sorted insert of key k into (v1<=v2<=v3), all uint32
#define KINS3(k, V1, V2, V3) do {                 \
    uint32_t _k = (k);                            \
    uint32_t _l = min(V1, _k);                    \
    uint32_t _h = max(V1, _k); V1 = _l;           \
    uint32_t _l2 = min(V2, _h);                   \
    uint32_t _h2 = max(V2, _h); V2 = _l2;         \
    V3 = min(V3, _h2);                            \
} while (0)

// ============ codebook -> fp16 pack ============
__global__ void conv_cb_kernel(const float* __restrict__ cb) {
    size_t i = (size_t)blockIdx.x * blockDim.x + threadIdx.x;  // float4 id (131072)
    float4 v = reinterpret_cast<const float4*>(cb)[i];
    __half2 h0 = __floats2half2_rn(v.x, v.y);
    __half2 h1 = __floats2half2_rn(v.z, v.w);
    uint2 H;
    H.x = *reinterpret_cast<uint32_t*>(&h0);
    H.y = *reinterpret_cast<uint32_t*>(&h1);
    *reinterpret_cast<uint2*>(g_e + i * 4) = H;
}

__global__ void ce_kernel(const float* __restrict__ cb) {
    int k = blockIdx.x * blockDim.x + threadIdx.x;
    const float4* p = reinterpret_cast<const float4*>(cb + (size_t)k * DB);
    float s = 0.f;
#pragma unroll
    for (int j = 0; j < 16; j++) {
        float4 v = p[j];
        s += v.x * v.x + v.y * v.y + v.z * v.z + v.w * v.w;
    }
    g_ce[k] = s;
}

// ============ fused HMMA distance + branchless top-3 + exact rescore ============
__global__ void __launch_bounds__(TPB, 2)
argmin_mma_kernel(const float* __restrict__ x, const float* __restrict__ cb,
                  float* __restrict__ out_idx) {
    extern __shared__ char smem[];
    const uint32_t sb = smem_u32(smem);
    const int t = threadIdx.x;
    const int wid = t >> 5, lane = t & 31;

    // B+ce chunk loader: 16KB B (1024x16B) + 512B ce (32x16B)
    auto load_B = [&](int kc, int stage) {
        const char* gsrc = reinterpret_cast<const char*>(g_e) + (size_t)kc * 128 * 128;
        uint32_t dbase = sb + SM_BST + stage * STAGE_SZ;
#pragma unroll
        for (int i = 0; i < 4; i++) {
            int id = t + i * TPB;
            int r = id >> 3, c = id & 7;
            CP_ASYNC16(dbase + r * 128 + ((c ^ (r & 7)) << 4), gsrc + r * 128 + c * 16);
        }
        if (t < 32)
            CP_ASYNC16(dbase + 16384 + t * 16,
                       reinterpret_cast<const char*>(g_ce + kc * 128) + t * 16);
    };
    load_B(0, 0); CP_COMMIT();
    load_B(1, 1); CP_COMMIT();
    load_B(2, 2); CP_COMMIT();

    // A tile: -2x fp16, swizzled 128B rows
    {
        const float4* xs = reinterpret_cast<const float4*>(x + (size_t)blockIdx.x * BM * DB);
#pragma unroll
        for (int i = 0; i < 8; i++) {
            int id = t + i * TPB;          // 2048 float4
            int r = id >> 4, fc = id & 15;
            float4 v = xs[id];
            __half2 h0 = __floats2half2_rn(-2.f * v.x, -2.f * v.y);
            __half2 h1 = __floats2half2_rn(-2.f * v.z, -2.f * v.w);
            uint2 H;
            H.x = *reinterpret_cast<uint32_t*>(&h0);
            H.y = *reinterpret_cast<uint32_t*>(&h1);
            int s = fc >> 1, hh = fc & 1;
            *reinterpret_cast<uint2*>(smem + r * 128 + ((s ^ (r & 7)) << 4) + hh * 8) = H;
        }
    }
    // per-row ||x||^2 -> cx smem (2 threads/row)
    {
        const int r = t >> 1, half = t & 1;
        const float4* xp = reinterpret_cast<const float4*>(
            x + ((size_t)blockIdx.x * BM + r) * DB + half * 32);
        float s = 0.f;
#pragma unroll
        for (int j = 0; j < 8; j++) {
            float4 v = xp[j];
            s += v.x * v.x + v.y * v.y + v.z * v.z + v.w * v.w;
        }
        s += __shfl_xor_sync(0xffffffffu, s, 1);
        if (half == 0) reinterpret_cast<float*>(smem + SM_CX)[r] = s;
    }

    // lane-invariant addressing (validated pattern from R3/R5)
    const int RW = wid * 16;
    const int rA = RW + ((lane >> 3) & 1) * 8 + (lane & 7);
    const uint32_t aRowBase = sb + rA * 128;
    const int aXor = rA & 7;
    const int akHalf = lane >> 4;
    const int nb_off = ((lane >> 4) & 1) * 8 + (lane & 7);
    const int kb = (lane >> 3) & 1;
    const int nX = nb_off & 7;
    const uint32_t bRow = nb_off * 128;
    const int q = lane & 3;

    __syncthreads();   // cx + A visible
    const float cxa = reinterpret_cast<const float*>(smem + SM_CX)[RW + (lane >> 2)];
    const float cxb = reinterpret_cast<const float*>(smem + SM_CX)[RW + (lane >> 2) + 8];

    uint32_t va1 = 0xFFFFFFFFu, va2 = 0xFFFFFFFFu, va3 = 0xFFFFFFFFu;
    uint32_t vb1 = 0xFFFFFFFFu, vb2 = 0xFFFFFFFFu, vb3 = 0xFFFFFFFFu;

    for (int kc = 0; kc < NCH; kc++) {
        const int stage = kc & 3;
        CP_WAITG(2);
        __syncthreads();

        const uint32_t bBuf = sb + SM_BST + stage * STAGE_SZ;
        const float2* ceS = reinterpret_cast<const float2*>(smem + SM_BST + stage * STAGE_SZ + 16384);

        // seed acc with ||e||^2 + ||x||^2
        float acc[64];
#pragma unroll
        for (int nf = 0; nf < 16; nf++) {
            float2 ce2 = ceS[nf * 4 + q];
            acc[nf * 4 + 0] = ce2.x + cxa;
            acc[nf * 4 + 1] = ce2.y + cxa;
            acc[nf * 4 + 2] = ce2.x + cxb;
            acc[nf * 4 + 3] = ce2.y + cxb;
        }

#pragma unroll
        for (int kk = 0; kk < 4; kk++) {
            uint32_t a0, a1, a2, a3;
            LDSM_X4(a0, a1, a2, a3, aRowBase + (((2 * kk + akHalf) ^ aXor) << 4));
#pragma unroll
            for (int g = 0; g < 8; g++) {
                uint32_t b0, b1, b2, b3;
                LDSM_X4(b0, b1, b2, b3, bBuf + g * 2048 + bRow + (((2 * kk + kb) ^ nX) << 4));
                MMA16816(&acc[(2 * g) * 4], a0, a1, a2, a3, b0, b1);
                MMA16816(&acc[(2 * g + 1) * 4], a0, a1, a2, a3, b2, b3);
            }
        }

        // branchless top-3: key = (score_bits & ~0x7FF) | L, L = kc<<5 | nf<<1 | p
        const uint32_t kcbase = (uint32_t)kc << 5;
#pragma unroll
        for (int nf = 0; nf < 16; nf++) {
            const uint32_t L0 = kcbase + (nf << 1);
            uint32_t k0 = (__float_as_uint(acc[nf * 4 + 0]) & 0xFFFFF800u) | L0;
            uint32_t k1 = (__float_as_uint(acc[nf * 4 + 1]) & 0xFFFFF800u) | (L0 + 1);
            uint32_t k2 = (__float_as_uint(acc[nf * 4 + 2]) & 0xFFFFF800u) | L0;
            uint32_t k3 = (__float_as_uint(acc[nf * 4 + 3]) & 0xFFFFF800u) | (L0 + 1);
            KINS3(k0, va1, va2, va3);
            KINS3(k1, va1, va2, va3);
            KINS3(k2, vb1, vb2, vb3);
            KINS3(k3, vb1, vb2, vb3);
        }

        if (kc + 3 < NCH) load_B(kc + 3, (kc + 3) & 3);
        CP_COMMIT();   // uniform group count
    }

    // decode keys -> codes, dump 12 candidates/row
    {
        int* cand = reinterpret_cast<int*>(smem + SM_CAND);
        const int ra = RW + (lane >> 2), rb = ra + 8;
        uint32_t ka[3] = {va1, va2, va3};
        uint32_t kbv[3] = {vb1, vb2, vb3};
#pragma unroll
        for (int j = 0; j < 3; j++) {
            uint32_t La = ka[j] & 0x7FFu;
            uint32_t Lb = kbv[j] & 0x7FFu;
            cand[ra * 12 + q * 3 + j] =
                (int)(((La >> 5) << 7) | (((La >> 1) & 15) << 3) | (q << 1) | (La & 1));
            cand[rb * 12 + q * 3 + j] =
                (int)(((Lb >> 5) << 7) | (((Lb >> 1) & 15) << 3) | (q << 1) | (Lb & 1));
        }
    }
    __syncthreads();

    // exact fp32 rescore: 2 threads/row, 32 dims each, 12 candidates
    {
        const int r = t >> 1, half = t & 1;
        const int* cand = reinterpret_cast<const int*>(smem + SM_CAND);
        float xr[32];
        const float4* xp = reinterpret_cast<const float4*>(
            x + ((size_t)blockIdx.x * BM + r) * DB + half * 32);
#pragma unroll
        for (int j = 0; j < 8; j++) {
            float4 v = xp[j];
            xr[j * 4] = v.x; xr[j * 4 + 1] = v.y; xr[j * 4 + 2] = v.z; xr[j * 4 + 3] = v.w;
        }
        float best = 3.4e38f;
        int bi = NK;
#pragma unroll 1
        for (int j = 0; j < 12; j++) {
            const int c = cand[r * 12 + j];
            const float4* ep = reinterpret_cast<const float4*>(cb + (size_t)c * DB + half * 32);
            float dot = 0.f;
#pragma unroll
            for (int u = 0; u < 8; u++) {
                float4 e = ep[u];
                dot += xr[u * 4] * e.x + xr[u * 4 + 1] * e.y + xr[u * 4 + 2] * e.z + xr[u * 4 + 3] * e.w;
            }
            dot += __shfl_xor_sync(0xffffffffu, dot, 1);
            const float score = fmaf(-2.f, dot, g_ce[c]);
            if (score < best || (score == best && c < bi)) { best = score; bi = c; }
        }
        if (half == 0) out_idx[(size_t)blockIdx.x * BM + r] = (float)bi;
    }
}

// ============ gather + loss ============
__global__ void gather_loss_kernel(const float* __restrict__ x, const float* __restrict__ cb,
                                   const float* __restrict__ idxf, float* __restrict__ outq) {
    __shared__ float rs[256];
    const int t = threadIdx.x;
    const int rl = t >> 2, seg = t & 3;
    const size_t row = (size_t)blockIdx.x * 64 + rl;
    const int k = (int)idxf[row];
    const float4* q  = reinterpret_cast<const float4*>(cb + (size_t)k * DB + seg * 16);
    const float4* xi = reinterpret_cast<const float4*>(x + row * DB + seg * 16);
    float4* o = reinterpret_cast<float4*>(outq + row * DB + seg * 16);
    float s = 0.f;
#pragma unroll
    for (int j = 0; j < 4; j++) {
        float4 qv = q[j], xv = xi[j];
        o[j] = qv;
        float dx = xv.x - qv.x, dy = xv.y - qv.y, dz = xv.z - qv.z, dw = xv.w - qv.w;
        s += dx * dx + dy * dy + dz * dz + dw * dw;
    }
    rs[t] = s;
    __syncthreads();
    for (int off = 128; off > 0; off >>= 1) {
        if (t < off) rs[t] += rs[t + off];
        __syncthreads();
    }
    if (t == 0) g_partial[blockIdx.x] = rs[0];
}

__global__ void loss_finalize_kernel(float* __restrict__ out_loss, int nparts, float scale) {
    __shared__ float rs[256];
    int t = threadIdx.x;
    float s = 0.f;
    for (int i = t; i < nparts; i += 256) s += g_partial[i];
    rs[t] = s;
    __syncthreads();
    for (int off = 128; off > 0; off >>= 1) {
        if (t < off) rs[t] += rs[t + off];
        __syncthreads();
    }
    if (t == 0) out_loss[0] = rs[0] * scale;
}

extern "C" void kernel_launch(void* const* d_in, const int* in_sizes, int n_in,
                              void* d_out, int out_size) {
    const float* x  = (const float*)d_in[0];
    const float* cb = (const float*)d_in[1];
    const int B = in_sizes[0] / DB;   // 65536
    (void)n_in; (void)out_size;

    float* out      = (float*)d_out;
    float* out_q    = out;
    float* out_loss = out + (size_t)B * DB;
    float* out_idx  = out_loss + 1;

    conv_cb_kernel<<<(NK * 16) / 256, 256>>>(cb);
    ce_kernel<<<NK / 256, 256>>>(cb);

    cudaFuncSetAttribute(argmin_mma_kernel, cudaFuncAttributeMaxDynamicSharedMemorySize, SM_TOT);
    argmin_mma_kernel<<<B / BM, TPB, SM_TOT>>>(x, cb, out_idx);

    gather_loss_kernel<<<B / 64, 256>>>(x, cb, out_idx, out_q);
    loss_finalize_kernel<<<1, 256>>>(out_loss, B / 64, 1.25f / ((float)B * DB));
}

// round 8
// speedup vs baseline: 4.0165x; 1.1053x over previous
#include <cuda_runtime.h>
#include <cuda_fp16.h>
#include <cstdint>

#define DB    64
#define NB    65536
#define NK    8192
#define BM    128
#define NCH   64            // K chunks of 128 codes
#define TPB   256

// smem (bytes): A 16KB @0 | cx 512B @16384 | 3 stages x 16896 @16896 | cand 6KB @67584
#define SM_CX    16384
#define SM_BST   16896
#define STAGE_SZ 16896      // 16KB B + 512B ce
#define SM_CAND  67584
#define SM_TOT   73728

__device__ __half g_e[(size_t)NK * DB];    // codebook fp16, row-contiguous 128B
__device__ float g_ce[NK];
__device__ float g_partial[1024];

static __device__ __forceinline__ uint32_t smem_u32(const void* p) {
    uint32_t a;
    asm("{ .reg .u64 t; cvta.to.shared.u64 t, %1; cvt.u32.u64 %0, t; }" : "=r"(a) : "l"(p));
    return a;
}

#define CP_ASYNC16(dst, src) asm volatile("cp.async.cg.shared.global [%0], [%1], 16;" :: "r"(dst), "l"(src))
#define CP_COMMIT()          asm volatile("cp.async.commit_group;" ::: "memory")
#define CP_WAITG(n)          asm volatile("cp.async.wait_group %0;" :: "n"(n) : "memory")

#define LDSM_X4(r0, r1, r2, r3, a) \
    asm volatile("ldmatrix.sync.aligned.m8n8.x4.shared.b16 {%0,%1,%2,%3}, [%4];" \
                 : "=r"(r0), "=r"(r1), "=r"(r2), "=r"(r3) : "r"(a))

#define MMA16816(d, a0, a1, a2, a3, b0, b1) \
    asm volatile("mma.sync.aligned.m16n8k16.row.col.f32.f16.f16.f32 " \
                 "{%0,%1,%2,%3}, {%4,%5,%6,%7}, {%8,%9}, {%0,%1,%2,%3};" \
                 : "+f"((d)[0]), "+f"((d)[1]), "+f"((d)[2]), "+f"((d)[3]) \
                 : "r"(a0), "r"(a1), "r"(a2), "r"(a3), "r"(b0), "r"(b1))

// branchless sorted insert of key k into (v1<=v2<=v3), all uint32
#define KINS3(k, V1, V2, V3) do {                 \
    uint32_t _k = (k);                            \
    uint32_t _l = min(V1, _k);                    \
    uint32_t _h = max(V1, _k); V1 = _l;           \
    uint32_t _l2 = min(V2, _h);                   \
    uint32_t _h2 = max(V2, _h); V2 = _l2;         \
    V3 = min(V3, _h2);                            \
} while (0)

// ============ codebook -> fp16 pack ============
__global__ void conv_cb_kernel(const float* __restrict__ cb) {
    size_t i = (size_t)blockIdx.x * blockDim.x + threadIdx.x;  // float4 id (131072)
    float4 v = reinterpret_cast<const float4*>(cb)[i];
    __half2 h0 = __floats2half2_rn(v.x, v.y);
    __half2 h1 = __floats2half2_rn(v.z, v.w);
    uint2 H;
    H.x = *reinterpret_cast<uint32_t*>(&h0);
    H.y = *reinterpret_cast<uint32_t*>(&h1);
    *reinterpret_cast<uint2*>(g_e + i * 4) = H;
}

__global__ void ce_kernel(const float* __restrict__ cb) {
    int k = blockIdx.x * blockDim.x + threadIdx.x;
    const float4* p = reinterpret_cast<const float4*>(cb + (size_t)k * DB);
    float s = 0.f;
#pragma unroll
    for (int j = 0; j < 16; j++) {
        float4 v = p[j];
        s += v.x * v.x + v.y * v.y + v.z * v.z + v.w * v.w;
    }
    g_ce[k] = s;
}

// ============ fused HMMA distance + branchless top-3 + exact rescore ============
__global__ void __launch_bounds__(TPB, 3)
argmin_mma_kernel(const float* __restrict__ x, const float* __restrict__ cb,
                  float* __restrict__ out_idx) {
    extern __shared__ char smem[];
    const uint32_t sb = smem_u32(smem);
    const int t = threadIdx.x;
    const int wid = t >> 5, lane = t & 31;

    // B+ce chunk loader: 16KB B (1024x16B) + 512B ce (32x16B)
    auto load_B = [&](int kc, int stage) {
        const char* gsrc = reinterpret_cast<const char*>(g_e) + (size_t)kc * 128 * 128;
        uint32_t dbase = sb + SM_BST + stage * STAGE_SZ;
#pragma unroll
        for (int i = 0; i < 4; i++) {
            int id = t + i * TPB;
            int r = id >> 3, c = id & 7;
            CP_ASYNC16(dbase + r * 128 + ((c ^ (r & 7)) << 4), gsrc + r * 128 + c * 16);
        }
        if (t < 32)
            CP_ASYNC16(dbase + 16384 + t * 16,
                       reinterpret_cast<const char*>(g_ce + kc * 128) + t * 16);
    };
    load_B(0, 0); CP_COMMIT();
    load_B(1, 1); CP_COMMIT();

    // A tile: -2x fp16, swizzled 128B rows
    {
        const float4* xs = reinterpret_cast<const float4*>(x + (size_t)blockIdx.x * BM * DB);
#pragma unroll
        for (int i = 0; i < 8; i++) {
            int id = t + i * TPB;          // 2048 float4
            int r = id >> 4, fc = id & 15;
            float4 v = xs[id];
            __half2 h0 = __floats2half2_rn(-2.f * v.x, -2.f * v.y);
            __half2 h1 = __floats2half2_rn(-2.f * v.z, -2.f * v.w);
            uint2 H;
            H.x = *reinterpret_cast<uint32_t*>(&h0);
            H.y = *reinterpret_cast<uint32_t*>(&h1);
            int s = fc >> 1, hh = fc & 1;
            *reinterpret_cast<uint2*>(smem + r * 128 + ((s ^ (r & 7)) << 4) + hh * 8) = H;
        }
    }
    // per-row ||x||^2 -> cx smem (2 threads/row)
    {
        const int r = t >> 1, half = t & 1;
        const float4* xp = reinterpret_cast<const float4*>(
            x + ((size_t)blockIdx.x * BM + r) * DB + half * 32);
        float s = 0.f;
#pragma unroll
        for (int j = 0; j < 8; j++) {
            float4 v = xp[j];
            s += v.x * v.x + v.y * v.y + v.z * v.z + v.w * v.w;
        }
        s += __shfl_xor_sync(0xffffffffu, s, 1);
        if (half == 0) reinterpret_cast<float*>(smem + SM_CX)[r] = s;
    }

    // lane-invariant addressing (validated pattern from R3/R5/R6)
    const int RW = wid * 16;
    const int rA = RW + ((lane >> 3) & 1) * 8 + (lane & 7);
    const uint32_t aRowBase = sb + rA * 128;
    const int aXor = rA & 7;
    const int akHalf = lane >> 4;
    const int nb_off = ((lane >> 4) & 1) * 8 + (lane & 7);
    const int kb = (lane >> 3) & 1;
    const int nX = nb_off & 7;
    const uint32_t bRow = nb_off * 128;
    const int q = lane & 3;

    __syncthreads();   // cx + A visible
    const float cxa = reinterpret_cast<const float*>(smem + SM_CX)[RW + (lane >> 2)];
    const float cxb = reinterpret_cast<const float*>(smem + SM_CX)[RW + (lane >> 2) + 8];

    // A fragments: chunk-invariant, load once
    uint32_t af[4][4];
#pragma unroll
    for (int kk = 0; kk < 4; kk++)
        LDSM_X4(af[kk][0], af[kk][1], af[kk][2], af[kk][3],
                aRowBase + (((2 * kk + akHalf) ^ aXor) << 4));

    uint32_t va1 = 0xFFFFFFFFu, va2 = 0xFFFFFFFFu, va3 = 0xFFFFFFFFu;
    uint32_t vb1 = 0xFFFFFFFFu, vb2 = 0xFFFFFFFFu, vb3 = 0xFFFFFFFFu;

    for (int kc = 0; kc < NCH; kc++) {
        const int stage = kc % 3;
        CP_WAITG(1);
        __syncthreads();

        const uint32_t bBuf = sb + SM_BST + stage * STAGE_SZ;
        const float2* ceS = reinterpret_cast<const float2*>(smem + SM_BST + stage * STAGE_SZ + 16384);
        const uint32_t kcbase = (uint32_t)kc << 5;

#pragma unroll
        for (int g = 0; g < 8; g++) {
            // seed acc with ||e||^2 + ||x||^2 (nf = 2g, 2g+1)
            float2 ce0 = ceS[(2 * g) * 4 + q];
            float2 ce1 = ceS[(2 * g + 1) * 4 + q];
            float acc[8];
            acc[0] = ce0.x + cxa; acc[1] = ce0.y + cxa;
            acc[2] = ce0.x + cxb; acc[3] = ce0.y + cxb;
            acc[4] = ce1.x + cxa; acc[5] = ce1.y + cxa;
            acc[6] = ce1.x + cxb; acc[7] = ce1.y + cxb;

#pragma unroll
            for (int kk = 0; kk < 4; kk++) {
                uint32_t b0, b1, b2, b3;
                LDSM_X4(b0, b1, b2, b3, bBuf + g * 2048 + bRow + (((2 * kk + kb) ^ nX) << 4));
                MMA16816(&acc[0], af[kk][0], af[kk][1], af[kk][2], af[kk][3], b0, b1);
                MMA16816(&acc[4], af[kk][0], af[kk][1], af[kk][2], af[kk][3], b2, b3);
            }

            // branchless top-3: key = (score_bits & ~0x7FF) | L, L = kc<<5 | nf<<1 | p
            const uint32_t L0 = kcbase + ((2 * g) << 1);
            const uint32_t L1 = kcbase + ((2 * g + 1) << 1);
            uint32_t k0 = (__float_as_uint(acc[0]) & 0xFFFFF800u) | L0;
            uint32_t k1 = (__float_as_uint(acc[1]) & 0xFFFFF800u) | (L0 + 1);
            uint32_t k2 = (__float_as_uint(acc[2]) & 0xFFFFF800u) | L0;
            uint32_t k3 = (__float_as_uint(acc[3]) & 0xFFFFF800u) | (L0 + 1);
            uint32_t k4 = (__float_as_uint(acc[4]) & 0xFFFFF800u) | L1;
            uint32_t k5 = (__float_as_uint(acc[5]) & 0xFFFFF800u) | (L1 + 1);
            uint32_t k6 = (__float_as_uint(acc[6]) & 0xFFFFF800u) | L1;
            uint32_t k7 = (__float_as_uint(acc[7]) & 0xFFFFF800u) | (L1 + 1);
            KINS3(k0, va1, va2, va3);
            KINS3(k1, va1, va2, va3);
            KINS3(k2, vb1, vb2, vb3);
            KINS3(k3, vb1, vb2, vb3);
            KINS3(k4, va1, va2, va3);
            KINS3(k5, va1, va2, va3);
            KINS3(k6, vb1, vb2, vb3);
            KINS3(k7, vb1, vb2, vb3);
        }

        if (kc + 2 < NCH) load_B(kc + 2, (kc + 2) % 3);
        CP_COMMIT();   // uniform group count
    }

    // decode keys -> codes, dump 12 candidates/row
    {
        int* cand = reinterpret_cast<int*>(smem + SM_CAND);
        const int ra = RW + (lane >> 2), rb = ra + 8;
        uint32_t ka[3] = {va1, va2, va3};
        uint32_t kbv[3] = {vb1, vb2, vb3};
#pragma unroll
        for (int j = 0; j < 3; j++) {
            uint32_t La = ka[j] & 0x7FFu;
            uint32_t Lb = kbv[j] & 0x7FFu;
            cand[ra * 12 + q * 3 + j] =
                (int)(((La >> 5) << 7) | (((La >> 1) & 15) << 3) | (q << 1) | (La & 1));
            cand[rb * 12 + q * 3 + j] =
                (int)(((Lb >> 5) << 7) | (((Lb >> 1) & 15) << 3) | (q << 1) | (Lb & 1));
        }
    }
    __syncthreads();

    // exact fp32 rescore: 2 threads/row, 32 dims each, 12 candidates
    {
        const int r = t >> 1, half = t & 1;
        const int* cand = reinterpret_cast<const int*>(smem + SM_CAND);
        float xr[32];
        const float4* xp = reinterpret_cast<const float4*>(
            x + ((size_t)blockIdx.x * BM + r) * DB + half * 32);
#pragma unroll
        for (int j = 0; j < 8; j++) {
            float4 v = xp[j];
            xr[j * 4] = v.x; xr[j * 4 + 1] = v.y; xr[j * 4 + 2] = v.z; xr[j * 4 + 3] = v.w;
        }
        float best = 3.4e38f;
        int bi = NK;
#pragma unroll 1
        for (int j = 0; j < 12; j++) {
            const int c = cand[r * 12 + j];
            const float4* ep = reinterpret_cast<const float4*>(cb + (size_t)c * DB + half * 32);
            float dot = 0.f;
#pragma unroll
            for (int u = 0; u < 8; u++) {
                float4 e = ep[u];
                dot += xr[u * 4] * e.x + xr[u * 4 + 1] * e.y + xr[u * 4 + 2] * e.z + xr[u * 4 + 3] * e.w;
            }
            dot += __shfl_xor_sync(0xffffffffu, dot, 1);
            const float score = fmaf(-2.f, dot, g_ce[c]);
            if (score < best || (score == best && c < bi)) { best = score; bi = c; }
        }
        if (half == 0) out_idx[(size_t)blockIdx.x * BM + r] = (float)bi;
    }
}

// ============ gather + loss ============
__global__ void gather_loss_kernel(const float* __restrict__ x, const float* __restrict__ cb,
                                   const float* __restrict__ idxf, float* __restrict__ outq) {
    __shared__ float rs[256];
    const int t = threadIdx.x;
    const int rl = t >> 2, seg = t & 3;
    const size_t row = (size_t)blockIdx.x * 64 + rl;
    const int k = (int)idxf[row];
    const float4* q  = reinterpret_cast<const float4*>(cb + (size_t)k * DB + seg * 16);
    const float4* xi = reinterpret_cast<const float4*>(x + row * DB + seg * 16);
    float4* o = reinterpret_cast<float4*>(outq + row * DB + seg * 16);
    float s = 0.f;
#pragma unroll
    for (int j = 0; j < 4; j++) {
        float4 qv = q[j], xv = xi[j];
        o[j] = qv;
        float dx = xv.x - qv.x, dy = xv.y - qv.y, dz = xv.z - qv.z, dw = xv.w - qv.w;
        s += dx * dx + dy * dy + dz * dz + dw * dw;
    }
    rs[t] = s;
    __syncthreads();
    for (int off = 128; off > 0; off >>= 1) {
        if (t < off) rs[t] += rs[t + off];
        __syncthreads();
    }
    if (t == 0) g_partial[blockIdx.x] = rs[0];
}

__global__ void loss_finalize_kernel(float* __restrict__ out_loss, int nparts, float scale) {
    __shared__ float rs[256];
    int t = threadIdx.x;
    float s = 0.f;
    for (int i = t; i < nparts; i += 256) s += g_partial[i];
    rs[t] = s;
    __syncthreads();
    for (int off = 128; off > 0; off >>= 1) {
        if (t < off) rs[t] += rs[t + off];
        __syncthreads();
    }
    if (t == 0) out_loss[0] = rs[0] * scale;
}

extern "C" void kernel_launch(void* const* d_in, const int* in_sizes, int n_in,
                              void* d_out, int out_size) {
    const float* x  = (const float*)d_in[0];
    const float* cb = (const float*)d_in[1];
    const int B = in_sizes[0] / DB;   // 65536
    (void)n_in; (void)out_size;

    float* out      = (float*)d_out;
    float* out_q    = out;
    float* out_loss = out + (size_t)B * DB;
    float* out_idx  = out_loss + 1;

    conv_cb_kernel<<<(NK * 16) / 256, 256>>>(cb);
    ce_kernel<<<NK / 256, 256>>>(cb);

    cudaFuncSetAttribute(argmin_mma_kernel, cudaFuncAttributeMaxDynamicSharedMemorySize, SM_TOT);
    argmin_mma_kernel<<<B / BM, TPB, SM_TOT>>>(x, cb, out_idx);

    gather_loss_kernel<<<B / 64, 256>>>(x, cb, out_idx, out_q);
    loss_finalize_kernel<<<1, 256>>>(out_loss, B / 64, 1.25f / ((float)B * DB));
}